// round 16
// baseline (speedup 1.0000x reference)
#include <cuda_runtime.h>

namespace {
constexpr int BS = 4, P = 4096, HW = 512 * 512;
constexpr int NT = 32;                      // 128-wide all-pairs tiles
constexpr int NTILES = NT * (NT + 1) / 2;   // 528
constexpr int APB = BS * NTILES;            // 2112 all-pairs blocks
constexpr int NCLS = 7, CAP = 768;          // class capacity (~8 sigma)
constexpr int NTC = 6;                      // 128-wide class tiles
constexpr int CT = NTC * (NTC + 1) / 2;     // 21
constexpr int SLB = BS * NCLS * CT;         // 588 same-label blocks
constexpr int GRID = 4 + APB + SLB;         // 2704
constexpr double NP = 8386560.0;            // P*(P-1)/2
}

// compile-time upper-tri decode tables (LDC, no per-thread loops)
struct TriA { unsigned char ti[NTILES]; unsigned char tj[NTILES]; };
constexpr TriA make_triA() {
    TriA r{}; int idx = 0;
    for (int i = 0; i < NT; i++) for (int j = i; j < NT; j++) { r.ti[idx] = (unsigned char)i; r.tj[idx] = (unsigned char)j; idx++; }
    return r;
}
struct TriC { unsigned char ti[CT]; unsigned char tj[CT]; };
constexpr TriC make_triC() {
    TriC r{}; int idx = 0;
    for (int i = 0; i < NTC; i++) for (int j = i; j < NTC; j++) { r.ti[idx] = (unsigned char)i; r.tj[idx] = (unsigned char)j; idx++; }
    return r;
}
__constant__ TriA c_triA = make_triA();
__constant__ TriC c_triC = make_triC();

__device__ float  g_ap[BS][P];              // a - 0.9 (compact, sample order)
__device__ float  g_nb[BS][P];              // -relu(a)
__device__ float  g_cls_a [BS][NCLS * CAP]; // label-grouped a (stable order)
__device__ float  g_cls_nb[BS][NCLS * CAP]; // label-grouped -relu(a)
__device__ int    g_Mc[BS][NCLS];           // padded class sizes (mult of 128)
__device__ double g_acc;                    // zero-init; reset each replay
__device__ unsigned g_cnt;
__device__ int    g_flag2;                  // compact arrays ready  (==4)
__device__ int    g_flag;                   // class partition ready (==4)

__global__ __launch_bounds__(256) void fused_k(const float* __restrict__ yp,
                                               const int*   __restrict__ yt,
                                               const int*   __restrict__ sm,
                                               float* __restrict__ out) {
    __shared__ float s_r[128];
    __shared__ float s_c[128];
    __shared__ unsigned long long sTot[16];
    __shared__ float s_part[8];

    int bid = blockIdx.x, tid = threadIdx.x;
    int lane = tid & 31, warp = tid >> 5;
    float contrib = 0.0f;

    if (bid < 4) {
        // ===== prep (streamed): gather compact arrays + label partition =====
        int b = bid;
        int base = tid * 16;
        unsigned long long cA = 0ull, cB = 0ull;   // packed 16-bit class counts
        #pragma unroll 8
        for (int k = 0; k < 16; k++) {
            int idx = sm[b * P + base + k];
            float a = yp[b * HW + idx];
            int   t = yt[b * HW + idx];
            g_ap[b][base + k] = a - 0.9f;          // emit compact arrays here
            g_nb[b][base + k] = -fmaxf(a, 0.0f);
            int c = min(max(t, 1), 7);
            if (c <= 4) cA += 1ull << ((c - 1) * 16);
            else        cB += 1ull << ((c - 5) * 16);
        }
        __threadfence();
        __syncthreads();
        if (tid == 0) atomicAdd(&g_flag2, 1);      // release all-pairs blocks

        unsigned long long iA = cA, iB = cB;       // warp inclusive scan
        #pragma unroll
        for (int off = 1; off < 32; off <<= 1) {
            unsigned long long vA = __shfl_up_sync(0xffffffffu, iA, off);
            unsigned long long vB = __shfl_up_sync(0xffffffffu, iB, off);
            if (lane >= off) { iA += vA; iB += vB; }
        }
        if (lane == 31) { sTot[warp] = iA; sTot[8 + warp] = iB; }
        __syncthreads();
        unsigned long long baseA = 0ull, baseB = 0ull, totA = 0ull, totB = 0ull;
        #pragma unroll
        for (int w = 0; w < 8; w++) {
            if (w < warp) { baseA += sTot[w]; baseB += sTot[8 + w]; }
            totA += sTot[w]; totB += sTot[8 + w];
        }
        unsigned long long curA = baseA + iA - cA;  // exclusive prefix
        unsigned long long curB = baseB + iB - cB;

        for (int i = tid; i < NCLS * CAP; i += 256) {
            g_cls_a [b][i] = -1e30f;   // pad pair contributes exactly -0.95 to G
            g_cls_nb[b][i] = -1e30f;
        }
        __syncthreads();

        // pass 2: reload (L2-hot) and stable-scatter into class arrays
        #pragma unroll 4
        for (int k = 0; k < 16; k++) {
            int idx = sm[b * P + base + k];
            float a = yp[b * HW + idx];
            int   t = yt[b * HW + idx];
            int   c = min(max(t, 1), 7);
            int off;
            if (c <= 4) { int sh = (c - 1) * 16; off = (int)((curA >> sh) & 0xFFFF); curA += 1ull << sh; }
            else        { int sh = (c - 5) * 16; off = (int)((curB >> sh) & 0xFFFF); curB += 1ull << sh; }
            if (off < CAP) {
                int slot = (c - 1) * CAP + off;
                g_cls_a [b][slot] = a;
                g_cls_nb[b][slot] = -fmaxf(a, 0.0f);
            }
        }
        __threadfence();
        __syncthreads();
        if (tid == 0) {
            double fake = 0.0;
            for (int c = 0; c < NCLS; c++) {
                int n = (c < 4) ? (int)((totA >> (c * 16)) & 0xFFFF)
                                : (int)((totB >> ((c - 4) * 16)) & 0xFFFF);
                if (n > CAP) n = CAP;
                int M = ((n + 127) / 128) * 128;
                g_Mc[b][c] = M;
                fake += 0.5 * ((double)M * (M - 1) - (double)n * (n - 1));
            }
            atomicAdd(&g_acc, 0.95 * fake);   // pad pairs each contributed -0.95
            __threadfence();
            atomicAdd(&g_flag, 1);            // release same-label blocks
        }
    } else if (bid < 4 + APB) {
        // ===== all-pairs 128x128 tile, COALESCED loads (R13-k2 body) ========
        // per pair: loss-0.05 = 5*relu(v)^2 - max(v,-0.9), v=(a_i-0.9)-relu(a_j)
        if (tid == 0) {
            while (((volatile int*)&g_flag2)[0] != 4) __nanosleep(64);
        }
        __syncthreads();
        __threadfence();

        int r = bid - 4;
        int b = r / NTILES, t = r % NTILES;
        int ti = c_triA.ti[t], tj = c_triA.tj[t];

        if (tid < 128) s_r[tid]       = g_ap[b][ti * 128 + tid];
        else           s_c[tid - 128] = g_nb[b][tj * 128 + (tid - 128)];
        __syncthreads();

        int tx = tid & 15, ty = tid >> 4;
        float a[8], nc[8];
        #pragma unroll
        for (int k = 0; k < 8; k++) {
            a[k]  = s_r[ty * 8 + k];
            nc[k] = s_c[tx * 8 + k];
        }

        float aU0 = 0.f, aU1 = 0.f, aW0 = 0.f, aW1 = 0.f;
        if (ti != tj) {
            #pragma unroll
            for (int jj = 0; jj < 8; jj++) {
                float cj = nc[jj];
                #pragma unroll
                for (int ii = 0; ii < 8; ii++) {
                    float v = a[ii] + cj;
                    float u = fmaxf(v, -0.9f);
                    float w = fmaxf(v, 0.0f);
                    if (ii & 1) { aU1 += u; aW1 = fmaf(w, w, aW1); }
                    else        { aU0 += u; aW0 = fmaf(w, w, aW0); }
                }
            }
        } else {
            int ib = ty * 8, jb = tx * 8;
            #pragma unroll
            for (int jj = 0; jj < 8; jj++) {
                float cj = nc[jj];
                #pragma unroll
                for (int ii = 0; ii < 8; ii++) {
                    if (jb + jj > ib + ii) {
                        float v = a[ii] + cj;
                        float u = fmaxf(v, -0.9f);
                        float w = fmaxf(v, 0.0f);
                        if (ii & 1) { aU1 += u; aW1 = fmaf(w, w, aW1); }
                        else        { aU0 += u; aW0 = fmaf(w, w, aW0); }
                    }
                }
            }
        }
        contrib = 5.0f * (aW0 + aW1) - (aU0 + aU1);
    } else {
        // ===== same-label class tiles (tail; partition ready long before) ===
        // G = 4p + z(15z-3) - 5w^2 - 0.95, p=relu(x), z=min(p,.1), w=relu(x-.9)
        if (tid == 0) {
            while (((volatile int*)&g_flag)[0] != 4) __nanosleep(64);
        }
        __syncthreads();
        __threadfence();

        int s = bid - 4 - APB;
        int b = s / (NCLS * CT); int rr = s % (NCLS * CT);
        int c = rr / CT;         int t = rr % CT;
        int ti = c_triC.ti[t], tj = c_triC.tj[t];
        int M = g_Mc[b][c];
        if (tj * 128 < M) {
            const float* ca = g_cls_a [b] + c * CAP;
            const float* cn = g_cls_nb[b] + c * CAP;
            if (tid < 128) s_r[tid]       = ca[ti * 128 + tid];
            else           s_c[tid - 128] = cn[tj * 128 + (tid - 128)];
            __syncthreads();
            int ty = tid >> 4, tx = tid & 15;
            float a8[8], n8[8];
            #pragma unroll
            for (int k = 0; k < 8; k++) { a8[k] = s_r[ty * 8 + k]; n8[k] = s_c[tx * 8 + k]; }
            float accP = 0.f, accZQ = 0.f, accW = 0.f;
            if (ti != tj) {
                #pragma unroll
                for (int jj = 0; jj < 8; jj++) {
                    float nbj = n8[jj];
                    #pragma unroll
                    for (int ii = 0; ii < 8; ii++) {
                        float x = a8[ii] + nbj;
                        float p = fmaxf(x, 0.0f);
                        float z = fminf(p, 0.1f);
                        float w = fmaxf(x - 0.9f, 0.0f);
                        float q = fmaf(z, 15.0f, -3.0f);
                        accP += p;
                        accZQ = fmaf(z, q, accZQ);
                        accW  = fmaf(w, w, accW);
                    }
                }
            } else {
                #pragma unroll
                for (int jj = 0; jj < 8; jj++) {
                    float nbj = n8[jj]; int cc = tx * 8 + jj;
                    #pragma unroll
                    for (int ii = 0; ii < 8; ii++) {
                        if (cc > ty * 8 + ii) {
                            float x = a8[ii] + nbj;
                            float p = fmaxf(x, 0.0f);
                            float z = fminf(p, 0.1f);
                            float w = fmaxf(x - 0.9f, 0.0f);
                            float q = fmaf(z, 15.0f, -3.0f);
                            accP += p;
                            accZQ = fmaf(z, q, accZQ);
                            accW  = fmaf(w, w, accW);
                        }
                    }
                }
            }
            contrib = fmaf(4.0f, accP, accZQ) - 5.0f * accW;
            if (tid == 0)
                contrib -= 0.95f * (float)((ti != tj) ? 128 * 128 : (128 * 127) / 2);
        }
    }

    // ===== common epilogue: block reduce + atomic + last-block finalize =====
    #pragma unroll
    for (int o = 16; o; o >>= 1)
        contrib += __shfl_xor_sync(0xffffffffu, contrib, o);
    if (lane == 0) s_part[warp] = contrib;
    __syncthreads();
    if (tid == 0) {
        float tot = 0.f;
        #pragma unroll
        for (int k = 0; k < 8; k++) tot += s_part[k];
        atomicAdd(&g_acc, (double)tot);
        __threadfence();
        unsigned cdone = atomicAdd(&g_cnt, 1u);
        if (cdone == (unsigned)(GRID - 1)) {
            double acc = *((volatile double*)&g_acc);
            out[0] = (float)(acc / (NP * (double)BS) + 0.05);
            g_acc   = 0.0;     // restore invariants for next replay
            g_cnt   = 0u;
            g_flag  = 0;
            g_flag2 = 0;
        }
    }
}

extern "C" void kernel_launch(void* const* d_in, const int* in_sizes, int n_in,
                              void* d_out, int out_size) {
    const float* yp = (const float*)d_in[0];
    const int*   yt = (const int*)d_in[1];
    const int*   sm = (const int*)d_in[2];

    fused_k<<<GRID, 256>>>(yp, yt, sm, (float*)d_out);
}

// round 17
// speedup vs baseline: 1.4732x; 1.4732x over previous
#include <cuda_runtime.h>

namespace {
constexpr int BS = 4, P = 4096, HW = 512 * 512;
constexpr int NRT = 32;                    // 128-row tiles per dim
constexpr int NCT = 16;                    // 256-col tiles per dim
constexpr int NTILES = 272;                // sum_{i=0}^{31} (16 - i/2)
constexpr int GRID = BS * NTILES;          // 1088 blocks
constexpr double NP = 8386560.0;           // P*(P-1)/2
}

// compile-time tile table: all (ti, tc) with the 256-col block intersecting j>i
struct Tiles { unsigned char ti[NTILES]; unsigned char tc[NTILES]; };
constexpr Tiles make_tiles() {
    Tiles r{}; int idx = 0;
    for (int i = 0; i < NRT; i++)
        for (int c = i / 2; c < NCT; c++) { r.ti[idx] = (unsigned char)i; r.tc[idx] = (unsigned char)c; idx++; }
    return r;
}
__constant__ Tiles c_tiles = make_tiles();

__device__ double g_acc;          // zero-init; reset by finalizing block
__device__ unsigned g_cnt;

__global__ __launch_bounds__(256) void pair_k(const float* __restrict__ yp,
                                              const int*   __restrict__ yt,
                                              const int*   __restrict__ sm,
                                              float* __restrict__ out) {
    __shared__ float s_a[128];  __shared__ int s_ta[128];    // rows: pred, label
    __shared__ float s_nc[256]; __shared__ int s_tc[256];    // cols: -relu, label
    __shared__ float s_part[8];

    int bid = blockIdx.x, tid = threadIdx.x;
    int b = bid / NTILES, t = bid % NTILES;
    int ti = c_tiles.ti[t], tc = c_tiles.tc[t];

    // fused gather: 384 scattered loads per block (vs 512 for two 128-tiles)
    {
        int ci = sm[b * P + tc * 256 + tid];
        s_nc[tid] = -fmaxf(yp[b * HW + ci], 0.0f);
        s_tc[tid] = yt[b * HW + ci];
        if (tid < 128) {
            int ri = sm[b * P + ti * 128 + tid];
            s_a[tid]  = yp[b * HW + ri];
            s_ta[tid] = yt[b * HW + ri];
        }
    }
    __syncthreads();

    int tx = tid & 15, ty = tid >> 4;      // 16 col-groups x 16 row-groups
    float a[8]; int ta[8]; float nc[16]; int tcl[16];
    #pragma unroll
    for (int k = 0; k < 8; k++) {
        a[k]  = s_a[ty * 8 + k];
        ta[k] = s_ta[ty * 8 + k];
    }
    #pragma unroll
    for (int k = 0; k < 16; k++) {
        nc[k]  = s_nc[tx * 16 + k];
        tcl[k] = s_tc[tx * 16 + k];
    }

    float acc0 = 0.0f, acc1 = 0.0f;
    bool interior = (2 * tc >= ti + 1);    // whole 128x256 block right of diagonal

    if (interior) {
        #pragma unroll
        for (int jj = 0; jj < 16; jj++) {
            float cj = nc[jj]; int tcv = tcl[jj];
            #pragma unroll
            for (int ii = 0; ii < 8; ii++) {
                float d = a[ii] + cj;                 // pred_i - relu(pred_j)
                float p = fmaxf(d, 0.0f);             // pi_pred
                float q = 1.0f - p;
                bool eq = (ta[ii] == tcv);
                float y = eq ? p : q;
                float z  = fminf(y, 0.1f);
                float t1 = fmaf(5.0f, z, -1.0f);      // FFMA-imm
                float h  = fmaf(z, t1, y);            // huber(y) exactly
                float s  = eq ? 3.0f : 1.0f;
                if (ii & 1) acc1 = fmaf(s, h, acc1);
                else        acc0 = fmaf(s, h, acc0);
            }
        }
    } else {
        // diagonal-containing block: mask c_local > r_local + off, off in {0,128}
        int off = 128 * (ti - 2 * tc);
        int rb = ty * 8 + off - tx * 16;   // mask: jj > rb + ii
        #pragma unroll
        for (int jj = 0; jj < 16; jj++) {
            float cj = nc[jj]; int tcv = tcl[jj];
            #pragma unroll
            for (int ii = 0; ii < 8; ii++) {
                if (jj > rb + ii) {
                    float d = a[ii] + cj;
                    float p = fmaxf(d, 0.0f);
                    float q = 1.0f - p;
                    bool eq = (ta[ii] == tcv);
                    float y = eq ? p : q;
                    float z  = fminf(y, 0.1f);
                    float t1 = fmaf(5.0f, z, -1.0f);
                    float h  = fmaf(z, t1, y);
                    float s  = eq ? 3.0f : 1.0f;
                    if (ii & 1) acc1 = fmaf(s, h, acc1);
                    else        acc0 = fmaf(s, h, acc0);
                }
            }
        }
    }
    float acc = acc0 + acc1;

    // block reduce + single atomic + last-block finalize (no waits anywhere)
    #pragma unroll
    for (int o = 16; o; o >>= 1)
        acc += __shfl_xor_sync(0xffffffffu, acc, o);
    int warp = tid >> 5, lane = tid & 31;
    if (lane == 0) s_part[warp] = acc;
    __syncthreads();
    if (tid == 0) {
        float tot = 0.0f;
        #pragma unroll
        for (int k = 0; k < 8; k++) tot += s_part[k];
        atomicAdd(&g_acc, (double)tot);
        __threadfence();
        unsigned cdone = atomicAdd(&g_cnt, 1u);
        if (cdone == (unsigned)(GRID - 1)) {
            double total = *((volatile double*)&g_acc);
            out[0] = (float)(total / (NP * (double)BS));
            g_acc = 0.0;      // restore invariants for next graph replay
            g_cnt = 0u;
        }
    }
}

extern "C" void kernel_launch(void* const* d_in, const int* in_sizes, int n_in,
                              void* d_out, int out_size) {
    const float* yp = (const float*)d_in[0];
    const int*   yt = (const int*)d_in[1];
    const int*   sm = (const int*)d_in[2];

    pair_k<<<GRID, 256>>>(yp, yt, sm, (float*)d_out);
}